// round 3
// baseline (speedup 1.0000x reference)
#include <cuda_runtime.h>
#include <cstdint>

// KANStressPredictor: elementwise over [B,T,3] f32 strain.
// Per point (s0,s1,s2):
//   c00=2s0+1, c11=2s1+1, c01=s2
//   det=c00*c11-c01^2, l=log2(det)
//   logJ = 0.5*ln2*l
//   mean=0.5*(c00+c11), rad=sqrt(0.25*(c00-c11)^2 + c01^2)
//   lambda0=mean-rad, lambda1=mean+rad   (eigenvalues of C, ascending)
//   out_k = exp2( ki0*(0.5*log2(lambda_k) - l/6) )   k=0,1
//   out_2 = logJ * ki1
//
// Memory-bound: 3x float4 load + 3x float4 store per thread (4 points).

__device__ __forceinline__ void kan_point(float s0, float s1, float s2,
                                          float ki0, float ki1,
                                          float& o0, float& o1, float& o2) {
    const float c00 = fmaf(2.0f, s0, 1.0f);
    const float c11 = fmaf(2.0f, s1, 1.0f);
    const float c01 = s2;

    const float det = fmaf(c00, c11, -c01 * c01);
    const float l   = __log2f(det);                 // log2(det)

    const float mean = 0.5f * (c00 + c11);
    const float hd   = 0.5f * (c00 - c11);
    const float rad  = sqrtf(fmaf(hd, hd, c01 * c01));

    const float lm = __log2f(mean - rad);           // log2(lambda0)
    const float lp = __log2f(mean + rad);           // log2(lambda1)

    const float e_aux = l * (-1.0f / 6.0f);         // log2(det^(-1/6))
    const float half_ki0 = 0.5f * ki0;
    const float base = ki0 * e_aux;

    o0 = exp2f(fmaf(half_ki0, lm, base));           // (sqrt(l0)*aux)^ki0
    o1 = exp2f(fmaf(half_ki0, lp, base));           // (sqrt(l1)*aux)^ki0
    o2 = (0.5f * 0.69314718055994531f) * l * ki1;   // log(sqrt(det)) * ki1
}

__global__ __launch_bounds__(256)
void kan_vec4_kernel(const float4* __restrict__ in, float4* __restrict__ out,
                     const float* __restrict__ ki0p, const float* __restrict__ ki1p,
                     int n_groups) {
    const int g = blockIdx.x * blockDim.x + threadIdx.x;
    if (g >= n_groups) return;

    const float ki0 = __ldg(ki0p);
    const float ki1 = __ldg(ki1p);

    // 3 contiguous float4 = 4 points (12 floats), front-batched for MLP.
    const float4 a = in[3 * g + 0];
    const float4 b = in[3 * g + 1];
    const float4 c = in[3 * g + 2];

    const float s[12] = {a.x, a.y, a.z, a.w,
                         b.x, b.y, b.z, b.w,
                         c.x, c.y, c.z, c.w};
    float o[12];

#pragma unroll
    for (int p = 0; p < 4; ++p) {
        kan_point(s[3 * p + 0], s[3 * p + 1], s[3 * p + 2],
                  ki0, ki1,
                  o[3 * p + 0], o[3 * p + 1], o[3 * p + 2]);
    }

    out[3 * g + 0] = make_float4(o[0], o[1], o[2],  o[3]);
    out[3 * g + 1] = make_float4(o[4], o[5], o[6],  o[7]);
    out[3 * g + 2] = make_float4(o[8], o[9], o[10], o[11]);
}

// Scalar tail (points not covered by the vec4 kernel). Normally 0 launches.
__global__ void kan_tail_kernel(const float* __restrict__ in, float* __restrict__ out,
                                const float* __restrict__ ki0p, const float* __restrict__ ki1p,
                                int start_point, int n_points) {
    const int p = start_point + blockIdx.x * blockDim.x + threadIdx.x;
    if (p >= n_points) return;
    const float ki0 = __ldg(ki0p);
    const float ki1 = __ldg(ki1p);
    float o0, o1, o2;
    kan_point(in[3 * p + 0], in[3 * p + 1], in[3 * p + 2], ki0, ki1, o0, o1, o2);
    out[3 * p + 0] = o0;
    out[3 * p + 1] = o1;
    out[3 * p + 2] = o2;
}

extern "C" void kernel_launch(void* const* d_in, const int* in_sizes, int n_in,
                              void* d_out, int out_size) {
    const float* strain = (const float*)d_in[0];
    const float* ki0p   = (const float*)d_in[1];
    const float* ki1p   = (const float*)d_in[2];
    float* out          = (float*)d_out;

    const int n_floats = in_sizes[0];          // B*T*3
    const int n_points = n_floats / 3;
    const int n_groups = n_points / 4;         // 4 points per thread
    const int tail     = n_points - n_groups * 4;

    if (n_groups > 0) {
        const int threads = 256;
        const int blocks  = (n_groups + threads - 1) / threads;
        kan_vec4_kernel<<<blocks, threads>>>(
            (const float4*)strain, (float4*)out, ki0p, ki1p, n_groups);
    }
    if (tail > 0) {
        kan_tail_kernel<<<1, 256>>>(strain, out, ki0p, ki1p, n_groups * 4, n_points);
    }
}